// round 1
// baseline (speedup 1.0000x reference)
#include <cuda_runtime.h>
#include <math.h>

#define BS2   2
#define NN    8192
#define NPT   128
#define CC    128
#define KGRID 64
#define M_TOT 8192        // NPT*KGRID per batch
#define KP1   136         // 131 padded to 136 (multiple of 8)

// ---------------- device scratch (no cudaMalloc allowed) ----------------
static __device__ float g_featT[(size_t)BS2*NN*CC];     // [b][n][c]
static __device__ float g_p2[(size_t)BS2*NN];
static __device__ float g_rel[(size_t)BS2*M_TOT*3];
static __device__ float g_cor[(size_t)BS2*M_TOT*3];
static __device__ int   g_nni[(size_t)BS2*M_TOT*3];
static __device__ float g_nnw[(size_t)BS2*M_TOT*3];
static __device__ float g_feat[(size_t)BS2*M_TOT*KP1];  // [b][m][k]
static __device__ float g_w1p[128*KP1];
static __device__ float g_h1[(size_t)BS2*M_TOT*128];    // [b][m][o]
static __device__ float g_pool[(size_t)BS2*256*NPT];    // [b][o][p]
static __device__ float g_y[(size_t)BS2*128*NPT];       // [b][o][p] pre-BN
static __device__ float g_z0[(size_t)BS2*128*NPT];
static __device__ float g_z1[(size_t)BS2*128*NPT];

// ---------------- decode: heading/center/lwh -> rel + corners ----------------
__global__ void decode_kernel(const float* __restrict__ cand,
                              const float* __restrict__ off,
                              const float* __restrict__ acls,
                              const float* __restrict__ ares)
{
    int t = blockIdx.x*blockDim.x + threadIdx.x;   // 16384 = b*8192 + p*64 + k
    int k  = t & 63;
    int bp = t >> 6;                                // 0..255
    const float* a = acls + bp*12;
    float best = a[0]; int bi = 0;
    #pragma unroll
    for (int j = 1; j < 12; j++) { float v = a[j]; if (v > best) { best = v; bi = j; } }
    float res = ares[bp*12 + bi];
    const float PI_F = 3.14159265358979323846f;
    float ang = (float)bi * (float)(2.0*3.14159265358979323846/12.0) + res;
    float heading = (ang > PI_F) ? (ang - 2.0f*PI_F) : ang;
    float s, c; sincosf(heading, &s, &c);

    const float* o6 = off + bp*6;
    float cx = cand[bp*3+0] + o6[0];
    float cy = cand[bp*3+1] + o6[1];
    float cz = cand[bp*3+2] + o6[2];
    float lx = fmaxf(o6[3]*2.0f, 0.1f);
    float ly = fmaxf(o6[4]*2.0f, 0.1f);
    float lz = fmaxf(o6[5]*2.0f, 0.1f);

    const float gs0 = -1.0f, gs1 = -1.0f/3.0f, gs2 = 1.0f/3.0f, gs3 = 1.0f;
    float gv[4] = {gs0, gs1, gs2, gs3};
    float gx = gv[(k>>4)&3] * lx;
    float gy = gv[(k>>2)&3] * ly;
    float gz = gv[k&3]      * lz;

    float rx = gx*c - gy*s;
    float ry = gx*s + gy*c;
    float rz = gz;

    size_t b3 = (size_t)t*3;
    g_rel[b3+0] = rx; g_rel[b3+1] = ry; g_rel[b3+2] = rz;
    g_cor[b3+0] = rx + cx; g_cor[b3+1] = ry + cy; g_cor[b3+2] = rz + cz;
}

// ---------------- transpose original_feature [b][c][n] -> [b][n][c] ----------------
__global__ void transpose_kernel(const float* __restrict__ f)
{
    __shared__ float tile[32][33];
    int b  = blockIdx.z;
    int n0 = blockIdx.x*32, c0 = blockIdx.y*32;
    int tx = threadIdx.x, ty = threadIdx.y;           // (32,8)
    const float* F = f + (size_t)b*CC*NN;
    #pragma unroll
    for (int j = 0; j < 32; j += 8)
        tile[ty+j][tx] = F[(size_t)(c0+ty+j)*NN + n0 + tx];
    __syncthreads();
    float* T = g_featT + (size_t)b*NN*CC;
    #pragma unroll
    for (int j = 0; j < 32; j += 8)
        T[(size_t)(n0+ty+j)*CC + c0 + tx] = tile[tx][ty+j];
}

__global__ void p2_kernel(const float* __restrict__ oxyz)
{
    int t = blockIdx.x*256 + threadIdx.x;             // 16384 = b*8192+n
    float x = oxyz[t*3], y = oxyz[t*3+1], z = oxyz[t*3+2];
    g_p2[t] = x*x + y*y + z*z;
}

__global__ void padw1_kernel(const float* __restrict__ w1)
{
    int t = blockIdx.x*256 + threadIdx.x;
    if (t < 128*KP1) {
        int o = t / KP1, k = t % KP1;
        g_w1p[t] = (k < 131) ? w1[o*131 + k] : 0.0f;
    }
}

// ---------------- three_nn: warp handles 2 corners ----------------
__device__ __forceinline__ void merge_write(float d0, float d1, float d2,
                                            int i0, int i1, int i2,
                                            volatile float* mw, volatile int* mi,
                                            int lane, const float* __restrict__ O,
                                            int b, int m, float cx, float cy, float cz)
{
    mw[lane*3+0] = d0; mi[lane*3+0] = i0;
    mw[lane*3+1] = d1; mi[lane*3+1] = i1;
    mw[lane*3+2] = d2; mi[lane*3+2] = i2;
    __syncwarp();
    int win[3];
    #pragma unroll
    for (int r = 0; r < 3; r++) {
        float v = 1e30f; int pos = 1<<30;
        #pragma unroll
        for (int j = 0; j < 3; j++) {
            int jj = lane + 32*j;
            float vv = mw[jj];
            if (vv < v || (vv == v && jj < pos)) { v = vv; pos = jj; }
        }
        #pragma unroll
        for (int offi = 16; offi; offi >>= 1) {
            float v2 = __shfl_xor_sync(0xffffffffu, v, offi);
            int   q2 = __shfl_xor_sync(0xffffffffu, pos, offi);
            if (v2 < v || (v2 == v && q2 < pos)) { v = v2; pos = q2; }
        }
        win[r] = mi[pos];
        if (lane == 0) mw[pos] = 2e30f;
        __syncwarp();
    }
    if (lane == 0) {
        float w[3], ssum = 0.0f;
        #pragma unroll
        for (int r = 0; r < 3; r++) {
            const float* P = O + (size_t)win[r]*3;
            float dx = P[0]-cx, dy = P[1]-cy, dz = P[2]-cz;
            float d = sqrtf(dx*dx + dy*dy + dz*dz);
            w[r] = 1.0f / (d + 1e-8f);
            ssum += w[r];
        }
        size_t base = ((size_t)b*M_TOT + m)*3;
        float inv = 1.0f/ssum;
        #pragma unroll
        for (int r = 0; r < 3; r++) { g_nni[base+r] = win[r]; g_nnw[base+r] = w[r]*inv; }
    }
    __syncwarp();
}

__global__ void three_nn_kernel(const float* __restrict__ oxyz)
{
    __shared__ float4 st[512];
    __shared__ float  mw[8][96];
    __shared__ int    mi[8][96];
    int tid = threadIdx.x, lane = tid & 31, wid = tid >> 5;
    int gw = blockIdx.x*8 + wid;                     // 0..8191
    int b  = gw >> 12;                               // 4096 warps per batch
    int mA = (gw & 4095) * 2;
    int mB = mA + 1;
    const float* O = oxyz + (size_t)b*NN*3;
    const float* Q = g_p2 + (size_t)b*NN;

    size_t bA = ((size_t)b*M_TOT + mA)*3;
    size_t bB = ((size_t)b*M_TOT + mB)*3;
    float cxA = g_cor[bA+0], cyA = g_cor[bA+1], czA = g_cor[bA+2];
    float cxB = g_cor[bB+0], cyB = g_cor[bB+1], czB = g_cor[bB+2];
    float c2A = cxA*cxA + cyA*cyA + czA*czA;
    float c2B = cxB*cxB + cyB*cyB + czB*czB;
    float axA = -2.0f*cxA, ayA = -2.0f*cyA, azA = -2.0f*czA;
    float axB = -2.0f*cxB, ayB = -2.0f*cyB, azB = -2.0f*czB;

    float dA0 = 1e30f, dA1 = 1e30f, dA2 = 1e30f; int iA0 = 0, iA1 = 0, iA2 = 0;
    float dB0 = 1e30f, dB1 = 1e30f, dB2 = 1e30f; int iB0 = 0, iB1 = 0, iB2 = 0;

    for (int t0 = 0; t0 < NN; t0 += 512) {
        __syncthreads();
        for (int i = tid; i < 512; i += 256) {
            int n = t0 + i;
            st[i] = make_float4(O[n*3], O[n*3+1], O[n*3+2], Q[n]);
        }
        __syncthreads();
        #pragma unroll 4
        for (int i = lane; i < 512; i += 32) {
            float4 pt = st[i];
            int n = t0 + i;
            float t = pt.w + c2A;
            t = fmaf(axA, pt.x, t); t = fmaf(ayA, pt.y, t); t = fmaf(azA, pt.z, t);
            if (t < dA2) {
                if (t < dA1) {
                    dA2 = dA1; iA2 = iA1;
                    if (t < dA0) { dA1 = dA0; iA1 = iA0; dA0 = t; iA0 = n; }
                    else         { dA1 = t;  iA1 = n; }
                } else { dA2 = t; iA2 = n; }
            }
            float u = pt.w + c2B;
            u = fmaf(axB, pt.x, u); u = fmaf(ayB, pt.y, u); u = fmaf(azB, pt.z, u);
            if (u < dB2) {
                if (u < dB1) {
                    dB2 = dB1; iB2 = iB1;
                    if (u < dB0) { dB1 = dB0; iB1 = iB0; dB0 = u; iB0 = n; }
                    else         { dB1 = u;  iB1 = n; }
                } else { dB2 = u; iB2 = n; }
            }
        }
    }
    merge_write(dA0, dA1, dA2, iA0, iA1, iA2, mw[wid], mi[wid], lane, O, b, mA, cxA, cyA, czA);
    merge_write(dB0, dB1, dB2, iB0, iB1, iB2, mw[wid], mi[wid], lane, O, b, mB, cxB, cyB, czB);
}

// ---------------- gather + interpolate + assemble feat [b][m][136] ----------------
__global__ void gather_kernel()
{
    int tid = threadIdx.x, lane = tid & 31, wid = tid >> 5;
    int gw = blockIdx.x*8 + wid;                     // 0..16383
    int b = gw >> 13, m = gw & 8191;
    size_t base3 = ((size_t)b*M_TOT + m)*3;
    int i0 = g_nni[base3+0], i1 = g_nni[base3+1], i2 = g_nni[base3+2];
    float w0 = g_nnw[base3+0], w1 = g_nnw[base3+1], w2 = g_nnw[base3+2];
    const float* r0 = g_featT + ((size_t)b*NN + i0)*CC;
    const float* r1 = g_featT + ((size_t)b*NN + i1)*CC;
    const float* r2 = g_featT + ((size_t)b*NN + i2)*CC;
    float* out = g_feat + ((size_t)b*M_TOT + m)*KP1;
    #pragma unroll
    for (int j = 0; j < 4; j++) {
        int c = lane + 32*j;
        out[3+c] = w0*r0[c] + w1*r1[c] + w2*r2[c];
    }
    if (lane < 3)       out[lane] = g_rel[base3 + lane];
    else if (lane < 8)  out[128 + lane] = 0.0f;      // pad cols 131..135
}

// ---------------- GEMM1: h1[m][o] = relu(feat[m][:] . w1p[o][:] + b1[o]) ----------------
__global__ void gemm1_kernel(const float* __restrict__ bias)
{
    int b  = blockIdx.z;
    int m0 = blockIdx.x*64, o0 = blockIdx.y*64;
    const float* F = g_feat + (size_t)b*M_TOT*KP1;
    __shared__ float Fs[8][64], Ws[8][64];
    int tid = threadIdx.x;
    int tx = tid & 15, ty = tid >> 4;
    int lr = tid >> 2, lc = (tid & 3)*2;
    float acc[4][4] = {};
    for (int kk = 0; kk < KP1; kk += 8) {
        __syncthreads();
        const float* fp = F + (size_t)(m0+lr)*KP1 + kk + lc;
        Fs[lc][lr] = fp[0]; Fs[lc+1][lr] = fp[1];
        const float* wp = g_w1p + (o0+lr)*KP1 + kk + lc;
        Ws[lc][lr] = wp[0]; Ws[lc+1][lr] = wp[1];
        __syncthreads();
        #pragma unroll
        for (int k = 0; k < 8; k++) {
            float4 av = *(const float4*)&Fs[k][tx*4];
            float4 bv = *(const float4*)&Ws[k][ty*4];
            float a4[4] = {av.x, av.y, av.z, av.w};
            float b4[4] = {bv.x, bv.y, bv.z, bv.w};
            #pragma unroll
            for (int i = 0; i < 4; i++)
                #pragma unroll
                for (int j = 0; j < 4; j++)
                    acc[i][j] = fmaf(a4[i], b4[j], acc[i][j]);
        }
    }
    float* H = g_h1 + (size_t)b*M_TOT*128;
    #pragma unroll
    for (int i = 0; i < 4; i++) {
        int m = m0 + tx*4 + i;
        #pragma unroll
        for (int j = 0; j < 4; j++) {
            int o = o0 + ty*4 + j;
            H[(size_t)m*128 + o] = fmaxf(acc[i][j] + bias[o], 0.0f);
        }
    }
}

// ---------------- GEMM2 + fused relu + maxpool over K=64 ----------------
__global__ void gemm2_pool_kernel(const float* __restrict__ W2, const float* __restrict__ bias)
{
    int b  = blockIdx.z;
    int p  = blockIdx.x;                 // one p per m-tile (m0 = p*64)
    int m0 = p*64, o0 = blockIdx.y*64;
    const float* H = g_h1 + (size_t)b*M_TOT*128;
    __shared__ float Hs[8][64], Ws[8][64];
    __shared__ int spool[64];
    int tid = threadIdx.x;
    int tx = tid & 15, ty = tid >> 4;
    int lr = tid >> 2, lc = (tid & 3)*2;
    if (tid < 64) spool[tid] = 0;
    float acc[4][4] = {};
    for (int kk = 0; kk < 128; kk += 8) {
        __syncthreads();
        const float* hp = H + (size_t)(m0+lr)*128 + kk + lc;
        Hs[lc][lr] = hp[0]; Hs[lc+1][lr] = hp[1];
        const float* wp = W2 + (o0+lr)*128 + kk + lc;
        Ws[lc][lr] = wp[0]; Ws[lc+1][lr] = wp[1];
        __syncthreads();
        #pragma unroll
        for (int k = 0; k < 8; k++) {
            float4 av = *(const float4*)&Hs[k][tx*4];
            float4 bv = *(const float4*)&Ws[k][ty*4];
            float a4[4] = {av.x, av.y, av.z, av.w};
            float b4[4] = {bv.x, bv.y, bv.z, bv.w};
            #pragma unroll
            for (int i = 0; i < 4; i++)
                #pragma unroll
                for (int j = 0; j < 4; j++)
                    acc[i][j] = fmaf(a4[i], b4[j], acc[i][j]);
        }
    }
    #pragma unroll
    for (int j = 0; j < 4; j++) {
        int ol = ty*4 + j;
        float bj = bias[o0 + ol];
        float lm = 0.0f;                                  // relu floor
        #pragma unroll
        for (int i = 0; i < 4; i++) lm = fmaxf(lm, acc[i][j] + bj);
        atomicMax(&spool[ol], __float_as_int(lm));        // lm >= 0: int order == float order
    }
    __syncthreads();
    if (tid < 64)
        g_pool[((size_t)b*256 + o0 + tid)*NPT + p] = __int_as_float(spool[tid]);
}

// ---------------- IoU head small layers ----------------
__global__ void lin_kernel(const float* __restrict__ W, const float* __restrict__ bias, int stage)
{
    int o = blockIdx.x, b = blockIdx.y, p = threadIdx.x;  // 128 threads
    const float* X = (stage == 0) ? g_pool : g_z0;
    int K = (stage == 0) ? 256 : 128;
    __shared__ float ws[256];
    for (int i = p; i < K; i += 128) ws[i] = W[o*K + i];
    __syncthreads();
    const float* Xb = X + (size_t)b*K*NPT;
    float acc = bias[o];
    #pragma unroll 8
    for (int c = 0; c < K; c++) acc = fmaf(ws[c], Xb[(size_t)c*NPT + p], acc);
    g_y[((size_t)b*128 + o)*NPT + p] = acc;
}

__global__ void bn_relu_kernel(const float* __restrict__ g, const float* __restrict__ be, int stage)
{
    int ch = blockIdx.x, tid = threadIdx.x;               // 256 threads = (b,p)
    int b = tid >> 7, p = tid & 127;
    size_t idx = ((size_t)b*128 + ch)*NPT + p;
    float v = g_y[idx];
    __shared__ float red[256];
    red[tid] = v; __syncthreads();
    #pragma unroll
    for (int s = 128; s > 0; s >>= 1) { if (tid < s) red[tid] += red[tid+s]; __syncthreads(); }
    float mean = red[0] * (1.0f/256.0f);
    __syncthreads();
    float d = v - mean;
    red[tid] = d*d; __syncthreads();
    #pragma unroll
    for (int s = 128; s > 0; s >>= 1) { if (tid < s) red[tid] += red[tid+s]; __syncthreads(); }
    float var = red[0] * (1.0f/256.0f);
    float z = d * rsqrtf(var + 1e-5f) * g[ch] + be[ch];
    float* Y = (stage == 0) ? g_z0 : g_z1;
    Y[idx] = fmaxf(z, 0.0f);
}

__global__ void final_kernel(const float* __restrict__ W, const float* __restrict__ bias,
                             float* __restrict__ out)
{
    int b = blockIdx.x, p = threadIdx.x;
    const float* Z = g_z1 + (size_t)b*128*NPT;
    float acc = bias[0];
    #pragma unroll 8
    for (int c = 0; c < 128; c++) acc = fmaf(W[c], Z[(size_t)c*NPT + p], acc);
    out[b*NPT + p] = acc;
}

// ---------------- launch ----------------
extern "C" void kernel_launch(void* const* d_in, const int* in_sizes, int n_in,
                              void* d_out, int out_size)
{
    const float* oxyz  = (const float*)d_in[0];
    const float* ofeat = (const float*)d_in[1];
    const float* cand  = (const float*)d_in[2];
    // d_in[3] = pred_cls (unused in forward)
    const float* poff  = (const float*)d_in[4];
    const float* pacls = (const float*)d_in[5];
    const float* pares = (const float*)d_in[6];
    const float* w1    = (const float*)d_in[7];
    const float* b1    = (const float*)d_in[8];
    const float* w2    = (const float*)d_in[9];
    const float* b2    = (const float*)d_in[10];
    const float* wi0   = (const float*)d_in[11];
    const float* bi0   = (const float*)d_in[12];
    const float* gi0   = (const float*)d_in[13];
    const float* bei0  = (const float*)d_in[14];
    const float* wi1   = (const float*)d_in[15];
    const float* bi1   = (const float*)d_in[16];
    const float* gi1   = (const float*)d_in[17];
    const float* bei1  = (const float*)d_in[18];
    const float* wi2   = (const float*)d_in[19];
    const float* bi2   = (const float*)d_in[20];
    float* out = (float*)d_out;

    decode_kernel<<<64, 256>>>(cand, poff, pacls, pares);
    transpose_kernel<<<dim3(256, 4, 2), dim3(32, 8)>>>(ofeat);
    p2_kernel<<<64, 256>>>(oxyz);
    padw1_kernel<<<68, 256>>>(w1);
    three_nn_kernel<<<1024, 256>>>(oxyz);
    gather_kernel<<<2048, 256>>>();
    gemm1_kernel<<<dim3(128, 2, 2), 256>>>(b1);
    gemm2_pool_kernel<<<dim3(128, 4, 2), 256>>>(w2, b2);
    lin_kernel<<<dim3(128, 2), 128>>>(wi0, bi0, 0);
    bn_relu_kernel<<<128, 256>>>(gi0, bei0, 0);
    lin_kernel<<<dim3(128, 2), 128>>>(wi1, bi1, 1);
    bn_relu_kernel<<<128, 256>>>(gi1, bei1, 1);
    final_kernel<<<2, 128>>>(wi2, bi2, out);
}